// round 4
// baseline (speedup 1.0000x reference)
#include <cuda_runtime.h>
#include <cuda_bf16.h>
#include <math_constants.h>
#include <cstdint>

#define Nn 64
#define Ll 1024
#define Hh 1024

// ---------------------------------------------------------------------------
// Device scratch
// ---------------------------------------------------------------------------
__device__ float g_dh[Nn * Hh];
__device__ float g_scoreP[4][Nn * Ll];
__device__ __align__(16) __nv_bfloat16 g_Bhi[Hh * Hh];
__device__ __align__(16) __nv_bfloat16 g_Blo[Hh * Hh];
__device__ __align__(16) __nv_bfloat16 g_Ehi[Nn * Ll * Hh];  // 128 MB
__device__ __align__(16) __nv_bfloat16 g_Elo[Nn * Ll * Hh];  // 128 MB
__device__ float4 g_ctxP[4][Nn * (Hh / 4)];

// ---------------------------------------------------------------------------
// Helpers
// ---------------------------------------------------------------------------
__device__ __forceinline__ uint32_t smem_u32(const void* p) {
    uint32_t a;
    asm("{ .reg .u64 t; cvta.to.shared.u64 t, %1; cvt.u32.u64 %0, t; }" : "=r"(a) : "l"(p));
    return a;
}
__device__ __forceinline__ float tanh_fast(float x) {
    float e = __expf(2.0f * x);
    return 1.0f - __fdividef(2.0f, e + 1.0f);
}
__device__ __forceinline__ unsigned pk2(__nv_bfloat16 a, __nv_bfloat16 b) {
    return (unsigned)__bfloat16_as_ushort(a) | ((unsigned)__bfloat16_as_ushort(b) << 16);
}
__device__ __forceinline__ void ldsm_x4(uint32_t* r, uint32_t addr) {
    asm volatile("ldmatrix.sync.aligned.m8n8.x4.shared.b16 {%0,%1,%2,%3}, [%4];"
                 : "=r"(r[0]), "=r"(r[1]), "=r"(r[2]), "=r"(r[3]) : "r"(addr));
}
__device__ __forceinline__ void mma_bf16(float* c, const uint32_t* a, uint32_t b0, uint32_t b1) {
    asm volatile("mma.sync.aligned.m16n8k16.row.col.f32.bf16.bf16.f32 "
                 "{%0,%1,%2,%3}, {%4,%5,%6,%7}, {%8,%9}, {%0,%1,%2,%3};"
                 : "+f"(c[0]), "+f"(c[1]), "+f"(c[2]), "+f"(c[3])
                 : "r"(a[0]), "r"(a[1]), "r"(a[2]), "r"(a[3]), "r"(b0), "r"(b1));
}
__device__ __forceinline__ void cp_async16(uint32_t dst, const void* src) {
    asm volatile("cp.async.cg.shared.global [%0], [%1], 16;" :: "r"(dst), "l"(src) : "memory");
}
#define CP_COMMIT() asm volatile("cp.async.commit_group;" ::: "memory")

// ---------------------------------------------------------------------------
// Split Ws -> bf16 hi/lo
// ---------------------------------------------------------------------------
__global__ __launch_bounds__(256) void bsplit_kernel(const float* __restrict__ Ws) {
    int i = blockIdx.x * 256 + threadIdx.x;
    float4 w = ((const float4*)Ws)[i];
    float vv[4] = {w.x, w.y, w.z, w.w};
    __nv_bfloat16 h[4], l[4];
#pragma unroll
    for (int j = 0; j < 4; ++j) {
        h[j] = __float2bfloat16_rn(vv[j]);
        l[j] = __float2bfloat16_rn(vv[j] - __bfloat162float(h[j]));
    }
    ((uint2*)g_Bhi)[i] = make_uint2(pk2(h[0], h[1]), pk2(h[2], h[3]));
    ((uint2*)g_Blo)[i] = make_uint2(pk2(l[0], l[1]), pk2(l[2], l[3]));
}

// ---------------------------------------------------------------------------
// Split E -> bf16 hi/lo (256 MB moved, ~65 us)
// ---------------------------------------------------------------------------
__global__ __launch_bounds__(256) void esplit_kernel(const float* __restrict__ E) {
    size_t i = (size_t)blockIdx.x * 256 + threadIdx.x;  // float4 index, 16.78M
    float4 w = ((const float4*)E)[i];
    float vv[4] = {w.x, w.y, w.z, w.w};
    __nv_bfloat16 h[4], l[4];
#pragma unroll
    for (int j = 0; j < 4; ++j) {
        h[j] = __float2bfloat16_rn(vv[j]);
        l[j] = __float2bfloat16_rn(vv[j] - __bfloat162float(h[j]));
    }
    ((uint2*)g_Ehi)[i] = make_uint2(pk2(h[0], h[1]), pk2(h[2], h[3]));
    ((uint2*)g_Elo)[i] = make_uint2(pk2(l[0], l[1]), pk2(l[2], l[3]));
}

// ---------------------------------------------------------------------------
// dh[n,k] = sum_h dec[n,h]*Wh[k,h]
// ---------------------------------------------------------------------------
__global__ __launch_bounds__(256) void dh_kernel(const float* __restrict__ dec,
                                                 const float* __restrict__ Wh) {
    int w = (blockIdx.x * blockDim.x + threadIdx.x) >> 5;
    int lane = threadIdx.x & 31;
    int n = w >> 10;
    int k = w & 1023;
    const float4* dp = (const float4*)(dec + (size_t)n * Hh);
    const float4* wp = (const float4*)(Wh + (size_t)k * Hh);
    float acc = 0.f;
#pragma unroll
    for (int it = 0; it < 8; ++it) {
        float4 a = dp[it * 32 + lane];
        float4 b = wp[it * 32 + lane];
        acc += a.x * b.x + a.y * b.y + a.z * b.z + a.w * b.w;
    }
#pragma unroll
    for (int o = 16; o; o >>= 1) acc += __shfl_xor_sync(0xffffffffu, acc, o);
    if (lane == 0) g_dh[w] = acc;
}

// ---------------------------------------------------------------------------
// Fused score kernel: bf16x3 mma.sync GEMM + tanh(.)·v epilogue.
// 3-stage cp.async pipeline, k32 chunks. CTA 128x256, 512 threads.
// ---------------------------------------------------------------------------
#define PITCHB 80                 // 32 bf16 data + 8 pad per row
#define A_BYTES (128 * PITCHB)    // 10240 per buffer
#define B_BYTES (256 * PITCHB)    // 20480 per buffer
#define STAGE_BYTES (2 * A_BYTES + 2 * B_BYTES)  // 61440
#define NSTAGE 3
#define SM_DH   0
#define SM_V    1024
#define SM_SRED 2048
#define SM_STG  4096
#define SM_TOTAL (SM_STG + NSTAGE * STAGE_BYTES)  // 188416

__global__ __launch_bounds__(512, 1) void score_kernel(const float* __restrict__ v) {
    extern __shared__ char smem[];
    const uint32_t sb = smem_u32(smem);
    const int tid = threadIdx.x;
    const int lane = tid & 31;
    const int wid = tid >> 5;
    const int wm = wid & 3;
    const int wn = wid >> 2;
    const int row0 = blockIdx.x * 128;
    const int n = row0 >> 10;
    const int jbase = blockIdx.y * 256;

    if (tid < 256) {
        ((float*)(smem + SM_DH))[tid] = g_dh[(n << 10) + jbase + tid];
        ((float*)(smem + SM_V))[tid] = v[jbase + tid];
    }

    // loader indices
    const int a_r = tid >> 2, a_q = tid & 3;              // 128 rows x 4 segs
    const int b_r0 = tid >> 2, b_q0 = tid & 3;            // first 128 B rows? no:
    const int b_r1 = (tid + 512) >> 2, b_q1 = (tid + 512) & 3;  // rows 128..255

    const __nv_bfloat16* Ah_src = g_Ehi + (size_t)(row0 + a_r) * Hh + a_q * 8;
    const __nv_bfloat16* Al_src = g_Elo + (size_t)(row0 + a_r) * Hh + a_q * 8;
    const __nv_bfloat16* Bh_src0 = g_Bhi + (size_t)(jbase + b_r0) * Hh + b_q0 * 8;
    const __nv_bfloat16* Bl_src0 = g_Blo + (size_t)(jbase + b_r0) * Hh + b_q0 * 8;
    const __nv_bfloat16* Bh_src1 = g_Bhi + (size_t)(jbase + b_r1) * Hh + b_q1 * 8;
    const __nv_bfloat16* Bl_src1 = g_Blo + (size_t)(jbase + b_r1) * Hh + b_q1 * 8;
    const uint32_t a_dst = (uint32_t)(a_r * PITCHB + a_q * 16);
    const uint32_t b_dst0 = (uint32_t)(b_r0 * PITCHB + b_q0 * 16);
    const uint32_t b_dst1 = (uint32_t)(b_r1 * PITCHB + b_q1 * 16);

    auto cp_stage = [&](int stg, int kb) {
        const uint32_t base = sb + SM_STG + (uint32_t)stg * STAGE_BYTES;
        cp_async16(base + a_dst, Ah_src + kb);
        cp_async16(base + A_BYTES + a_dst, Al_src + kb);
        cp_async16(base + 2 * A_BYTES + b_dst0, Bh_src0 + kb);
        cp_async16(base + 2 * A_BYTES + b_dst1, Bh_src1 + kb);
        cp_async16(base + 2 * A_BYTES + B_BYTES + b_dst0, Bl_src0 + kb);
        cp_async16(base + 2 * A_BYTES + B_BYTES + b_dst1, Bl_src1 + kb);
    };

    float acc[2][8][4];
#pragma unroll
    for (int mt = 0; mt < 2; ++mt)
#pragma unroll
        for (int nt = 0; nt < 8; ++nt)
#pragma unroll
            for (int e = 0; e < 4; ++e) acc[mt][nt][e] = 0.f;

    // ldmatrix per-thread offsets
    const uint32_t a_off = (uint32_t)((lane & 15) * PITCHB + ((lane >> 4) << 3) * 2);
    const uint32_t b_off =
        (uint32_t)((((lane >> 4) << 3) + (lane & 7)) * PITCHB + (((lane >> 3) & 1) << 3) * 2);

    // prologue: stages 0,1
    cp_stage(0, 0);
    CP_COMMIT();
    cp_stage(1, 32);
    CP_COMMIT();

    for (int c = 0; c < 32; ++c) {
        if (c < 31)
            asm volatile("cp.async.wait_group 1;" ::: "memory");
        else
            asm volatile("cp.async.wait_group 0;" ::: "memory");
        __syncthreads();
        if (c + 2 < 32) {
            cp_stage((c + 2) % NSTAGE, (c + 2) * 32);
            CP_COMMIT();
        }

        const uint32_t base = sb + SM_STG + (uint32_t)(c % NSTAGE) * STAGE_BYTES;
        const uint32_t sAh = base;
        const uint32_t sAl = base + A_BYTES;
        const uint32_t sBh = base + 2 * A_BYTES;
        const uint32_t sBl = sBh + B_BYTES;
#pragma unroll
        for (int ks = 0; ks < 2; ++ks) {
            const uint32_t ko = (uint32_t)(ks * 32);
            uint32_t ah[2][4], al[2][4];
#pragma unroll
            for (int mt = 0; mt < 2; ++mt) {
                uint32_t ao = (uint32_t)((wm * 32 + mt * 16) * PITCHB) + a_off + ko;
                ldsm_x4(ah[mt], sAh + ao);
                ldsm_x4(al[mt], sAl + ao);
            }
#pragma unroll
            for (int np = 0; np < 4; ++np) {
                uint32_t bo = (uint32_t)((wn * 64 + np * 16) * PITCHB) + b_off + ko;
                uint32_t bh[4], bl[4];
                ldsm_x4(bh, sBh + bo);
                ldsm_x4(bl, sBl + bo);
#pragma unroll
                for (int mt = 0; mt < 2; ++mt) {
                    mma_bf16(acc[mt][np * 2 + 0], ah[mt], bh[0], bh[1]);
                    mma_bf16(acc[mt][np * 2 + 1], ah[mt], bh[2], bh[3]);
                    mma_bf16(acc[mt][np * 2 + 0], al[mt], bh[0], bh[1]);
                    mma_bf16(acc[mt][np * 2 + 1], al[mt], bh[2], bh[3]);
                    mma_bf16(acc[mt][np * 2 + 0], ah[mt], bl[0], bl[1]);
                    mma_bf16(acc[mt][np * 2 + 1], ah[mt], bl[2], bl[3]);
                }
            }
        }
    }

    // epilogue
    const float* dhs = (const float*)(smem + SM_DH);
    const float* vs = (const float*)(smem + SM_V);
    float part[4] = {0.f, 0.f, 0.f, 0.f};
#pragma unroll
    for (int mt = 0; mt < 2; ++mt)
#pragma unroll
        for (int nt = 0; nt < 8; ++nt)
#pragma unroll
            for (int e = 0; e < 4; ++e) {
                int col = wn * 64 + nt * 8 + (lane & 3) * 2 + (e & 1);
                part[mt * 2 + (e >> 1)] += tanh_fast(acc[mt][nt][e] + dhs[col]) * vs[col];
            }
#pragma unroll
    for (int p = 0; p < 4; ++p) {
        part[p] += __shfl_xor_sync(0xffffffffu, part[p], 1);
        part[p] += __shfl_xor_sync(0xffffffffu, part[p], 2);
    }
    float* sred = (float*)(smem + SM_SRED);
    if ((lane & 3) == 0) {
#pragma unroll
        for (int mt = 0; mt < 2; ++mt)
#pragma unroll
            for (int rr = 0; rr < 2; ++rr) {
                int row = wm * 32 + mt * 16 + (lane >> 2) + rr * 8;
                sred[row * 4 + wn] = part[mt * 2 + rr];
            }
    }
    __syncthreads();
    if (tid < 128) {
        g_scoreP[blockIdx.y][row0 + tid] =
            sred[tid * 4] + sred[tid * 4 + 1] + sred[tid * 4 + 2] + sred[tid * 4 + 3];
    }
}

// ---------------------------------------------------------------------------
// Masked softmax
// ---------------------------------------------------------------------------
__global__ __launch_bounds__(256) void softmax_kernel(const int* __restrict__ mask,
                                                      float* __restrict__ attn) {
    __shared__ float red[256];
    const int n = blockIdx.x;
    const int tid = threadIdx.x;

    float s[4];
    int msk[4];
    float lmax = -CUDART_INF_F;
#pragma unroll
    for (int q = 0; q < 4; ++q) {
        int l = tid + 256 * q;
        msk[q] = mask[n * Ll + l];
        s[q] = g_scoreP[0][n * Ll + l] + g_scoreP[1][n * Ll + l] +
               g_scoreP[2][n * Ll + l] + g_scoreP[3][n * Ll + l];
        if (!msk[q]) lmax = fmaxf(lmax, s[q]);
    }
    red[tid] = lmax;
    __syncthreads();
    for (int o = 128; o; o >>= 1) {
        if (tid < o) red[tid] = fmaxf(red[tid], red[tid + o]);
        __syncthreads();
    }
    const float mx = red[0];
    __syncthreads();

    float p[4];
    float lsum = 0.f;
#pragma unroll
    for (int q = 0; q < 4; ++q) {
        p[q] = msk[q] ? 0.f : __expf(s[q] - mx);
        lsum += p[q];
    }
    red[tid] = lsum;
    __syncthreads();
    for (int o = 128; o; o >>= 1) {
        if (tid < o) red[tid] += red[tid + o];
        __syncthreads();
    }
    const float inv = 1.0f / red[0];
#pragma unroll
    for (int q = 0; q < 4; ++q) attn[n * Ll + tid + 256 * q] = p[q] * inv;
}

// ---------------------------------------------------------------------------
// Context + reduce
// ---------------------------------------------------------------------------
__global__ __launch_bounds__(128) void context_kernel(const float* __restrict__ E,
                                                      const float* __restrict__ attn) {
    __shared__ float sa[256];
    __shared__ float4 red[128];
    const int n = blockIdx.x, hc = blockIdx.y, lc = blockIdx.z;
    const int tid = threadIdx.x;
    sa[tid] = attn[n * Ll + lc * 256 + tid];
    sa[tid + 128] = attn[n * Ll + lc * 256 + tid + 128];
    __syncthreads();

    const int c = tid & 31;
    const int lg = tid >> 5;
    const float4* Ep = (const float4*)(E + (size_t)n * Ll * Hh) +
                       (size_t)(lc * 256) * 256 + hc * 32 + c;
    float4 acc = make_float4(0.f, 0.f, 0.f, 0.f);
    const int l0 = lg * 64;
#pragma unroll 4
    for (int l = 0; l < 64; ++l) {
        float a = sa[l0 + l];
        float4 e = Ep[(size_t)(l0 + l) * 256];
        acc.x += a * e.x; acc.y += a * e.y;
        acc.z += a * e.z; acc.w += a * e.w;
    }
    red[tid] = acc;
    __syncthreads();
    if (tid < 32) {
        float4 s = red[tid];
#pragma unroll
        for (int g = 1; g < 4; ++g) {
            float4 o = red[tid + 32 * g];
            s.x += o.x; s.y += o.y; s.z += o.z; s.w += o.w;
        }
        g_ctxP[lc][n * 256 + hc * 32 + tid] = s;
    }
}

__global__ __launch_bounds__(256) void ctx_reduce_kernel(float4* __restrict__ ctx4) {
    int i = blockIdx.x * 256 + threadIdx.x;
    float4 a = g_ctxP[0][i], b = g_ctxP[1][i], c = g_ctxP[2][i], d = g_ctxP[3][i];
    ctx4[i] = make_float4(a.x + b.x + c.x + d.x, a.y + b.y + c.y + d.y,
                          a.z + b.z + c.z + d.z, a.w + b.w + c.w + d.w);
}

// ---------------------------------------------------------------------------
extern "C" void kernel_launch(void* const* d_in, const int* in_sizes, int n_in,
                              void* d_out, int out_size) {
    const float* dec  = (const float*)d_in[0];
    const float* E    = (const float*)d_in[1];
    const int*   mask = (const int*)  d_in[2];
    const float* Wh   = (const float*)d_in[3];
    const float* Ws   = (const float*)d_in[4];
    const float* v    = (const float*)d_in[5];

    float* out  = (float*)d_out;
    float* ctx  = out;
    float* attn = out + Nn * Hh;

    cudaFuncSetAttribute(score_kernel, cudaFuncAttributeMaxDynamicSharedMemorySize, SM_TOTAL);

    bsplit_kernel<<<(Hh * Hh / 4) / 256, 256>>>(Ws);
    esplit_kernel<<<(Nn * Ll * Hh / 4) / 256, 256>>>(E);
    dh_kernel<<<(Nn * Hh * 32) / 256, 256>>>(dec, Wh);
    score_kernel<<<dim3((Nn * Ll) / 128, 4), 512, SM_TOTAL>>>(v);
    softmax_kernel<<<Nn, 256>>>(mask, attn);
    context_kernel<<<dim3(Nn, Hh / 128, 4), 128>>>(E, attn);
    ctx_reduce_kernel<<<(Nn * Hh / 4) / 256, 256>>>((float4*)ctx);
}

// round 5
// speedup vs baseline: 1.1820x; 1.1820x over previous
#include <cuda_runtime.h>
#include <cuda_bf16.h>
#include <math_constants.h>
#include <cstdint>

#define Nn 64
#define Ll 1024
#define Hh 1024

// ---------------------------------------------------------------------------
// Device scratch
// ---------------------------------------------------------------------------
__device__ float g_dh[Nn * Hh];
__device__ float g_scoreP[8][Nn * Ll];
__device__ __align__(16) __nv_bfloat16 g_Bhi[Hh * Hh];
__device__ __align__(16) __nv_bfloat16 g_Blo[Hh * Hh];
__device__ __align__(16) __nv_bfloat16 g_Ehi[Nn * Ll * Hh];
__device__ __align__(16) __nv_bfloat16 g_Elo[Nn * Ll * Hh];
__device__ float4 g_ctxP[4][Nn * (Hh / 4)];

// ---------------------------------------------------------------------------
// Helpers
// ---------------------------------------------------------------------------
__device__ __forceinline__ uint32_t smem_u32(const void* p) {
    uint32_t a;
    asm("{ .reg .u64 t; cvta.to.shared.u64 t, %1; cvt.u32.u64 %0, t; }" : "=r"(a) : "l"(p));
    return a;
}
__device__ __forceinline__ float tanh_fast(float x) {
    float e = __expf(2.0f * x);
    return 1.0f - __fdividef(2.0f, e + 1.0f);
}
__device__ __forceinline__ unsigned pk2(__nv_bfloat16 a, __nv_bfloat16 b) {
    return (unsigned)__bfloat16_as_ushort(a) | ((unsigned)__bfloat16_as_ushort(b) << 16);
}
__device__ __forceinline__ void ldsm_x4(uint32_t* r, uint32_t addr) {
    asm volatile("ldmatrix.sync.aligned.m8n8.x4.shared.b16 {%0,%1,%2,%3}, [%4];"
                 : "=r"(r[0]), "=r"(r[1]), "=r"(r[2]), "=r"(r[3]) : "r"(addr));
}
__device__ __forceinline__ void mma_bf16(float* c, const uint32_t* a, uint32_t b0, uint32_t b1) {
    asm volatile("mma.sync.aligned.m16n8k16.row.col.f32.bf16.bf16.f32 "
                 "{%0,%1,%2,%3}, {%4,%5,%6,%7}, {%8,%9}, {%0,%1,%2,%3};"
                 : "+f"(c[0]), "+f"(c[1]), "+f"(c[2]), "+f"(c[3])
                 : "r"(a[0]), "r"(a[1]), "r"(a[2]), "r"(a[3]), "r"(b0), "r"(b1));
}
__device__ __forceinline__ void cp_async16(uint32_t dst, const void* src) {
    asm volatile("cp.async.cg.shared.global [%0], [%1], 16;" :: "r"(dst), "l"(src) : "memory");
}
#define CP_COMMIT() asm volatile("cp.async.commit_group;" ::: "memory")

// 64B-row swizzle: seg' = seg ^ ((row>>1)&3). Conflict-free for STS (4 segs of
// one row distinct) and for ldmatrix phases (8 rows x 1 seg -> 8 distinct
// 16B units mod 128B).
__device__ __forceinline__ uint32_t swz(int row, int seg) {
    return (uint32_t)(row * 64 + ((seg ^ ((row >> 1) & 3)) << 4));
}

// ---------------------------------------------------------------------------
// Split Ws -> bf16 hi/lo
// ---------------------------------------------------------------------------
__global__ __launch_bounds__(256) void bsplit_kernel(const float* __restrict__ Ws) {
    int i = blockIdx.x * 256 + threadIdx.x;
    float4 w = ((const float4*)Ws)[i];
    float vv[4] = {w.x, w.y, w.z, w.w};
    __nv_bfloat16 h[4], l[4];
#pragma unroll
    for (int j = 0; j < 4; ++j) {
        h[j] = __float2bfloat16_rn(vv[j]);
        l[j] = __float2bfloat16_rn(vv[j] - __bfloat162float(h[j]));
    }
    ((uint2*)g_Bhi)[i] = make_uint2(pk2(h[0], h[1]), pk2(h[2], h[3]));
    ((uint2*)g_Blo)[i] = make_uint2(pk2(l[0], l[1]), pk2(l[2], l[3]));
}

// ---------------------------------------------------------------------------
// Split E -> bf16 hi/lo
// ---------------------------------------------------------------------------
__global__ __launch_bounds__(256) void esplit_kernel(const float* __restrict__ E) {
    size_t i = (size_t)blockIdx.x * 256 + threadIdx.x;
    float4 w = ((const float4*)E)[i];
    float vv[4] = {w.x, w.y, w.z, w.w};
    __nv_bfloat16 h[4], l[4];
#pragma unroll
    for (int j = 0; j < 4; ++j) {
        h[j] = __float2bfloat16_rn(vv[j]);
        l[j] = __float2bfloat16_rn(vv[j] - __bfloat162float(h[j]));
    }
    ((uint2*)g_Ehi)[i] = make_uint2(pk2(h[0], h[1]), pk2(h[2], h[3]));
    ((uint2*)g_Elo)[i] = make_uint2(pk2(l[0], l[1]), pk2(l[2], l[3]));
}

// ---------------------------------------------------------------------------
// dh[n,k] = sum_h dec[n,h]*Wh[k,h]
// ---------------------------------------------------------------------------
__global__ __launch_bounds__(256) void dh_kernel(const float* __restrict__ dec,
                                                 const float* __restrict__ Wh) {
    int w = (blockIdx.x * blockDim.x + threadIdx.x) >> 5;
    int lane = threadIdx.x & 31;
    int n = w >> 10;
    int k = w & 1023;
    const float4* dp = (const float4*)(dec + (size_t)n * Hh);
    const float4* wp = (const float4*)(Wh + (size_t)k * Hh);
    float acc = 0.f;
#pragma unroll
    for (int it = 0; it < 8; ++it) {
        float4 a = dp[it * 32 + lane];
        float4 b = wp[it * 32 + lane];
        acc += a.x * b.x + a.y * b.y + a.z * b.z + a.w * b.w;
    }
#pragma unroll
    for (int o = 16; o; o >>= 1) acc += __shfl_xor_sync(0xffffffffu, acc, o);
    if (lane == 0) g_dh[w] = acc;
}

// ---------------------------------------------------------------------------
// Fused score kernel: bf16x3 mma.sync GEMM + tanh(.)·v epilogue.
// CTA 128x128, 256 threads (8 warps), 3-stage cp.async, swizzled 64B rows,
// 2 CTAs/SM. MMAs grouped by term for RAW distance 8.
// ---------------------------------------------------------------------------
#define A_BYTES 8192              // 128 rows x 64B
#define B_BYTES 8192
#define STAGE_BYTES (2 * A_BYTES + 2 * B_BYTES)  // 32768
#define NSTAGE 3
#define SM_DH   0
#define SM_V    512
#define SM_SRED 1024
#define SM_STG  2048
#define SM_TOTAL (SM_STG + NSTAGE * STAGE_BYTES)  // 100352

__global__ __launch_bounds__(256, 2) void score_kernel(const float* __restrict__ v) {
    extern __shared__ char smem[];
    const uint32_t sb = smem_u32(smem);
    const int tid = threadIdx.x;
    const int lane = tid & 31;
    const int wid = tid >> 5;
    const int wm = wid & 3;     // rows wm*32..+31
    const int wn = wid >> 2;    // cols wn*64..+63 (0..1)
    const int row0 = blockIdx.x * 128;
    const int n = row0 >> 10;
    const int jbase = blockIdx.y * 128;

    if (tid < 128) {
        ((float*)(smem + SM_DH))[tid] = g_dh[(n << 10) + jbase + tid];
        ((float*)(smem + SM_V))[tid] = v[jbase + tid];
    }

    // loader: 2 segments per thread (idx, idx+256); idx -> row=idx>>2, seg=idx&3
    const int l_row0 = tid >> 2, l_seg0 = tid & 3;
    const int l_row1 = (tid + 256) >> 2, l_seg1 = (tid + 256) & 3;
    const uint32_t l_dst0 = swz(l_row0, l_seg0);
    const uint32_t l_dst1 = swz(l_row1, l_seg1);
    const size_t gA0 = (size_t)(row0 + l_row0) * Hh + l_seg0 * 8;
    const size_t gA1 = (size_t)(row0 + l_row1) * Hh + l_seg1 * 8;
    const size_t gB0 = (size_t)(jbase + l_row0) * Hh + l_seg0 * 8;
    const size_t gB1 = (size_t)(jbase + l_row1) * Hh + l_seg1 * 8;

    auto cp_stage = [&](int stg, int kb) {
        const uint32_t base = sb + SM_STG + (uint32_t)stg * STAGE_BYTES;
        cp_async16(base + l_dst0, g_Ehi + gA0 + kb);
        cp_async16(base + l_dst1, g_Ehi + gA1 + kb);
        cp_async16(base + A_BYTES + l_dst0, g_Elo + gA0 + kb);
        cp_async16(base + A_BYTES + l_dst1, g_Elo + gA1 + kb);
        cp_async16(base + 2 * A_BYTES + l_dst0, g_Bhi + gB0 + kb);
        cp_async16(base + 2 * A_BYTES + l_dst1, g_Bhi + gB1 + kb);
        cp_async16(base + 3 * A_BYTES + l_dst0, g_Blo + gB0 + kb);
        cp_async16(base + 3 * A_BYTES + l_dst1, g_Blo + gB1 + kb);
    };

    float acc[2][8][4];
#pragma unroll
    for (int mt = 0; mt < 2; ++mt)
#pragma unroll
        for (int nt = 0; nt < 8; ++nt)
#pragma unroll
            for (int e = 0; e < 4; ++e) acc[mt][nt][e] = 0.f;

    // per-warp ldmatrix row/xor precompute
    int r_mt[2], x_mt[2];
#pragma unroll
    for (int mt = 0; mt < 2; ++mt) {
        r_mt[mt] = wm * 32 + mt * 16 + (lane & 15);
        x_mt[mt] = (r_mt[mt] >> 1) & 3;
    }
    int rb_np[4], xb_np[4];
#pragma unroll
    for (int np = 0; np < 4; ++np) {
        rb_np[np] = wn * 64 + np * 16 + ((lane >> 4) << 3) + (lane & 7);
        xb_np[np] = (rb_np[np] >> 1) & 3;
    }
    const int a_seg0 = lane >> 4;
    const int b_seg0 = (lane >> 3) & 1;

    cp_stage(0, 0);
    CP_COMMIT();
    cp_stage(1, 32);
    CP_COMMIT();

    for (int c = 0; c < 32; ++c) {
        if (c < 31)
            asm volatile("cp.async.wait_group 1;" ::: "memory");
        else
            asm volatile("cp.async.wait_group 0;" ::: "memory");
        __syncthreads();
        if (c + 2 < 32) {
            cp_stage((c + 2) % NSTAGE, (c + 2) * 32);
            CP_COMMIT();
        }

        const uint32_t base = sb + SM_STG + (uint32_t)(c % NSTAGE) * STAGE_BYTES;
        const uint32_t sAh = base;
        const uint32_t sAl = base + A_BYTES;
        const uint32_t sBh = base + 2 * A_BYTES;
        const uint32_t sBl = base + 3 * A_BYTES;

#pragma unroll
        for (int ks = 0; ks < 2; ++ks) {
            const int aseg = a_seg0 + ks * 2;
            const int bseg = b_seg0 + ks * 2;
            uint32_t ah[2][4], al[2][4];
#pragma unroll
            for (int mt = 0; mt < 2; ++mt) {
                uint32_t ao = (uint32_t)(r_mt[mt] * 64 + ((aseg ^ x_mt[mt]) << 4));
                ldsm_x4(ah[mt], sAh + ao);
                ldsm_x4(al[mt], sAl + ao);
            }
            // process np in halves of 2 -> peak B regs 16, RAW distance 8
#pragma unroll
            for (int h = 0; h < 2; ++h) {
                uint32_t bh[2][4];
#pragma unroll
                for (int q = 0; q < 2; ++q) {
                    int np = h * 2 + q;
                    uint32_t bo = (uint32_t)(rb_np[np] * 64 + ((bseg ^ xb_np[np]) << 4));
                    ldsm_x4(bh[q], sBh + bo);
                }
                // term1: Ah x Bh (8 distinct accs)
#pragma unroll
                for (int q = 0; q < 2; ++q)
#pragma unroll
                    for (int mt = 0; mt < 2; ++mt) {
                        int nt = (h * 2 + q) * 2;
                        mma_bf16(acc[mt][nt + 0], ah[mt], bh[q][0], bh[q][1]);
                        mma_bf16(acc[mt][nt + 1], ah[mt], bh[q][2], bh[q][3]);
                    }
                // term2: Al x Bh
#pragma unroll
                for (int q = 0; q < 2; ++q)
#pragma unroll
                    for (int mt = 0; mt < 2; ++mt) {
                        int nt = (h * 2 + q) * 2;
                        mma_bf16(acc[mt][nt + 0], al[mt], bh[q][0], bh[q][1]);
                        mma_bf16(acc[mt][nt + 1], al[mt], bh[q][2], bh[q][3]);
                    }
                // term3: Ah x Bl
                uint32_t bl[2][4];
#pragma unroll
                for (int q = 0; q < 2; ++q) {
                    int np = h * 2 + q;
                    uint32_t bo = (uint32_t)(rb_np[np] * 64 + ((bseg ^ xb_np[np]) << 4));
                    ldsm_x4(bl[q], sBl + bo);
                }
#pragma unroll
                for (int q = 0; q < 2; ++q)
#pragma unroll
                    for (int mt = 0; mt < 2; ++mt) {
                        int nt = (h * 2 + q) * 2;
                        mma_bf16(acc[mt][nt + 0], ah[mt], bl[q][0], bl[q][1]);
                        mma_bf16(acc[mt][nt + 1], ah[mt], bl[q][2], bl[q][3]);
                    }
            }
        }
    }

    // epilogue: score partial = sum_j tanh(eh + dh)*v
    const float* dhs = (const float*)(smem + SM_DH);
    const float* vs = (const float*)(smem + SM_V);
    float part[4] = {0.f, 0.f, 0.f, 0.f};
#pragma unroll
    for (int mt = 0; mt < 2; ++mt)
#pragma unroll
        for (int nt = 0; nt < 8; ++nt)
#pragma unroll
            for (int e = 0; e < 4; ++e) {
                int col = wn * 64 + nt * 8 + (lane & 3) * 2 + (e & 1);
                part[mt * 2 + (e >> 1)] += tanh_fast(acc[mt][nt][e] + dhs[col]) * vs[col];
            }
#pragma unroll
    for (int p = 0; p < 4; ++p) {
        part[p] += __shfl_xor_sync(0xffffffffu, part[p], 1);
        part[p] += __shfl_xor_sync(0xffffffffu, part[p], 2);
    }
    float* sred = (float*)(smem + SM_SRED);
    if ((lane & 3) == 0) {
#pragma unroll
        for (int mt = 0; mt < 2; ++mt)
#pragma unroll
            for (int rr = 0; rr < 2; ++rr) {
                int row = wm * 32 + mt * 16 + (lane >> 2) + rr * 8;
                sred[row * 2 + wn] = part[mt * 2 + rr];
            }
    }
    __syncthreads();
    if (tid < 128) {
        g_scoreP[blockIdx.y][row0 + tid] = sred[tid * 2] + sred[tid * 2 + 1];
    }
}

// ---------------------------------------------------------------------------
// Masked softmax (sums 8 col-block partials)
// ---------------------------------------------------------------------------
__global__ __launch_bounds__(256) void softmax_kernel(const int* __restrict__ mask,
                                                      float* __restrict__ attn) {
    __shared__ float red[256];
    const int n = blockIdx.x;
    const int tid = threadIdx.x;

    float s[4];
    int msk[4];
    float lmax = -CUDART_INF_F;
#pragma unroll
    for (int q = 0; q < 4; ++q) {
        int l = tid + 256 * q;
        msk[q] = mask[n * Ll + l];
        float acc = 0.f;
#pragma unroll
        for (int p = 0; p < 8; ++p) acc += g_scoreP[p][n * Ll + l];
        s[q] = acc;
        if (!msk[q]) lmax = fmaxf(lmax, s[q]);
    }
    red[tid] = lmax;
    __syncthreads();
    for (int o = 128; o; o >>= 1) {
        if (tid < o) red[tid] = fmaxf(red[tid], red[tid + o]);
        __syncthreads();
    }
    const float mx = red[0];
    __syncthreads();

    float p[4];
    float lsum = 0.f;
#pragma unroll
    for (int q = 0; q < 4; ++q) {
        p[q] = msk[q] ? 0.f : __expf(s[q] - mx);
        lsum += p[q];
    }
    red[tid] = lsum;
    __syncthreads();
    for (int o = 128; o; o >>= 1) {
        if (tid < o) red[tid] += red[tid + o];
        __syncthreads();
    }
    const float inv = 1.0f / red[0];
#pragma unroll
    for (int q = 0; q < 4; ++q) attn[n * Ll + tid + 256 * q] = p[q] * inv;
}

// ---------------------------------------------------------------------------
// Context + reduce
// ---------------------------------------------------------------------------
__global__ __launch_bounds__(128) void context_kernel(const float* __restrict__ E,
                                                      const float* __restrict__ attn) {
    __shared__ float sa[256];
    __shared__ float4 red[128];
    const int n = blockIdx.x, hc = blockIdx.y, lc = blockIdx.z;
    const int tid = threadIdx.x;
    sa[tid] = attn[n * Ll + lc * 256 + tid];
    sa[tid + 128] = attn[n * Ll + lc * 256 + tid + 128];
    __syncthreads();

    const int c = tid & 31;
    const int lg = tid >> 5;
    const float4* Ep = (const float4*)(E + (size_t)n * Ll * Hh) +
                       (size_t)(lc * 256) * 256 + hc * 32 + c;
    float4 acc = make_float4(0.f, 0.f, 0.f, 0.f);
    const int l0 = lg * 64;
#pragma unroll 4
    for (int l = 0; l < 64; ++l) {
        float a = sa[l0 + l];
        float4 e = Ep[(size_t)(l0 + l) * 256];
        acc.x += a * e.x; acc.y += a * e.y;
        acc.z += a * e.z; acc.w += a * e.w;
    }
    red[tid] = acc;
    __syncthreads();
    if (tid < 32) {
        float4 s = red[tid];
#pragma unroll
        for (int g = 1; g < 4; ++g) {
            float4 o = red[tid + 32 * g];
            s.x += o.x; s.y += o.y; s.z += o.z; s.w += o.w;
        }
        g_ctxP[lc][n * 256 + hc * 32 + tid] = s;
    }
}

__global__ __launch_bounds__(256) void ctx_reduce_kernel(float4* __restrict__ ctx4) {
    int i = blockIdx.x * 256 + threadIdx.x;
    float4 a = g_ctxP[0][i], b = g_ctxP[1][i], c = g_ctxP[2][i], d = g_ctxP[3][i];
    ctx4[i] = make_float4(a.x + b.x + c.x + d.x, a.y + b.y + c.y + d.y,
                          a.z + b.z + c.z + d.z, a.w + b.w + c.w + d.w);
}

// ---------------------------------------------------------------------------
extern "C" void kernel_launch(void* const* d_in, const int* in_sizes, int n_in,
                              void* d_out, int out_size) {
    const float* dec  = (const float*)d_in[0];
    const float* E    = (const float*)d_in[1];
    const int*   mask = (const int*)  d_in[2];
    const float* Wh   = (const float*)d_in[3];
    const float* Ws   = (const float*)d_in[4];
    const float* v    = (const float*)d_in[5];

    float* out  = (float*)d_out;
    float* ctx  = out;
    float* attn = out + Nn * Hh;

    cudaFuncSetAttribute(score_kernel, cudaFuncAttributeMaxDynamicSharedMemorySize, SM_TOTAL);

    bsplit_kernel<<<(Hh * Hh / 4) / 256, 256>>>(Ws);
    esplit_kernel<<<(Nn * Ll * Hh / 4) / 256, 256>>>(E);
    dh_kernel<<<(Nn * Hh * 32) / 256, 256>>>(dec, Wh);
    score_kernel<<<dim3((Nn * Ll) / 128, 8), 256, SM_TOTAL>>>(v);
    softmax_kernel<<<Nn, 256>>>(mask, attn);
    context_kernel<<<dim3(Nn, Hh / 128, 4), 128>>>(E, attn);
    ctx_reduce_kernel<<<(Nn * Hh / 4) / 256, 256>>>((float4*)ctx);
}

// round 6
// speedup vs baseline: 2.4671x; 2.0872x over previous
#include <cuda_runtime.h>
#include <cuda_fp16.h>
#include <math_constants.h>
#include <cstdint>

#define Nn 64
#define Ll 1024
#define Hh 1024

// ---------------------------------------------------------------------------
// Device scratch
// ---------------------------------------------------------------------------
__device__ float g_dh[Nn * Hh];
__device__ float g_scoreP[8][Nn * Ll];
__device__ __align__(16) __half g_Bh[Hh * Hh];        // Ws fp16 (2 MB)
__device__ __align__(16) __half g_Eh[Nn * Ll * Hh];   // E fp16 (128 MB)
__device__ float4 g_ctxP[4][Nn * (Hh / 4)];

// ---------------------------------------------------------------------------
// Helpers
// ---------------------------------------------------------------------------
__device__ __forceinline__ uint32_t smem_u32(const void* p) {
    uint32_t a;
    asm("{ .reg .u64 t; cvta.to.shared.u64 t, %1; cvt.u32.u64 %0, t; }" : "=r"(a) : "l"(p));
    return a;
}
__device__ __forceinline__ float tanh_fast(float x) {
    float e = __expf(2.0f * x);
    return 1.0f - __fdividef(2.0f, e + 1.0f);
}
__device__ __forceinline__ void ldsm_x4(uint32_t* r, uint32_t addr) {
    asm volatile("ldmatrix.sync.aligned.m8n8.x4.shared.b16 {%0,%1,%2,%3}, [%4];"
                 : "=r"(r[0]), "=r"(r[1]), "=r"(r[2]), "=r"(r[3]) : "r"(addr));
}
__device__ __forceinline__ void mma_f16(float* c, const uint32_t* a, uint32_t b0, uint32_t b1) {
    asm volatile("mma.sync.aligned.m16n8k16.row.col.f32.f16.f16.f32 "
                 "{%0,%1,%2,%3}, {%4,%5,%6,%7}, {%8,%9}, {%0,%1,%2,%3};"
                 : "+f"(c[0]), "+f"(c[1]), "+f"(c[2]), "+f"(c[3])
                 : "r"(a[0]), "r"(a[1]), "r"(a[2]), "r"(a[3]), "r"(b0), "r"(b1));
}
__device__ __forceinline__ void cp_async16(uint32_t dst, const void* src) {
    asm volatile("cp.async.cg.shared.global [%0], [%1], 16;" :: "r"(dst), "l"(src) : "memory");
}
#define CP_COMMIT() asm volatile("cp.async.commit_group;" ::: "memory")

// 64B-row swizzle (verified R5): seg' = seg ^ ((row>>1)&3)
__device__ __forceinline__ uint32_t swz(int row, int seg) {
    return (uint32_t)(row * 64 + ((seg ^ ((row >> 1) & 3)) << 4));
}

// ---------------------------------------------------------------------------
// Convert Ws -> fp16
// ---------------------------------------------------------------------------
__global__ __launch_bounds__(256) void bconv_kernel(const float* __restrict__ Ws) {
    size_t i = (size_t)blockIdx.x * 256 + threadIdx.x;  // 2 float4 per thread
    float4 w0 = ((const float4*)Ws)[2 * i];
    float4 w1 = ((const float4*)Ws)[2 * i + 1];
    __half2 h[4];
    h[0] = __floats2half2_rn(w0.x, w0.y);
    h[1] = __floats2half2_rn(w0.z, w0.w);
    h[2] = __floats2half2_rn(w1.x, w1.y);
    h[3] = __floats2half2_rn(w1.z, w1.w);
    ((uint4*)g_Bh)[i] = *(uint4*)h;
}

// ---------------------------------------------------------------------------
// Convert E -> fp16 (read 256 MB, write 128 MB)
// ---------------------------------------------------------------------------
__global__ __launch_bounds__(256) void econv_kernel(const float* __restrict__ E) {
    size_t i = (size_t)blockIdx.x * 256 + threadIdx.x;  // 2 float4 per thread
    float4 w0 = ((const float4*)E)[2 * i];
    float4 w1 = ((const float4*)E)[2 * i + 1];
    __half2 h[4];
    h[0] = __floats2half2_rn(w0.x, w0.y);
    h[1] = __floats2half2_rn(w0.z, w0.w);
    h[2] = __floats2half2_rn(w1.x, w1.y);
    h[3] = __floats2half2_rn(w1.z, w1.w);
    ((uint4*)g_Eh)[i] = *(uint4*)h;
}

// ---------------------------------------------------------------------------
// dh[n,k] = sum_h dec[n,h]*Wh[k,h]
// ---------------------------------------------------------------------------
__global__ __launch_bounds__(256) void dh_kernel(const float* __restrict__ dec,
                                                 const float* __restrict__ Wh) {
    int w = (blockIdx.x * blockDim.x + threadIdx.x) >> 5;
    int lane = threadIdx.x & 31;
    int n = w >> 10;
    int k = w & 1023;
    const float4* dp = (const float4*)(dec + (size_t)n * Hh);
    const float4* wp = (const float4*)(Wh + (size_t)k * Hh);
    float acc = 0.f;
#pragma unroll
    for (int it = 0; it < 8; ++it) {
        float4 a = dp[it * 32 + lane];
        float4 b = wp[it * 32 + lane];
        acc += a.x * b.x + a.y * b.y + a.z * b.z + a.w * b.w;
    }
#pragma unroll
    for (int o = 16; o; o >>= 1) acc += __shfl_xor_sync(0xffffffffu, acc, o);
    if (lane == 0) g_dh[w] = acc;
}

// ---------------------------------------------------------------------------
// Fused score kernel: single-term fp16 mma.sync GEMM + tanh(.)·v epilogue.
// CTA 128x128, 256 threads, 6-stage cp.async, 4 j-blocks per CTA, 2 CTAs/SM.
// ---------------------------------------------------------------------------
#define A_BYTES 8192              // 128 rows x 64B (32 fp16 k-els)
#define STAGE_BYTES (2 * A_BYTES) // A + B
#define NSTAGE 6
#define SM_DH   0
#define SM_V    512
#define SM_SRED 1024
#define SM_STG  2048
#define SM_TOTAL (SM_STG + NSTAGE * STAGE_BYTES)  // 100352

__global__ __launch_bounds__(256, 2) void score_kernel(const float* __restrict__ v) {
    extern __shared__ char smem[];
    const uint32_t sb = smem_u32(smem);
    const int tid = threadIdx.x;
    const int lane = tid & 31;
    const int wid = tid >> 5;
    const int wm = wid & 3;    // rows wm*32..+31
    const int wn = wid >> 2;   // cols wn*64..+63
    const int row0 = blockIdx.x * 128;
    const int n = row0 >> 10;

    // loader indices (2 16B segs per thread)
    const int l_row0 = tid >> 2, l_seg0 = tid & 3;
    const int l_row1 = (tid + 256) >> 2, l_seg1 = (tid + 256) & 3;
    const uint32_t l_dst0 = swz(l_row0, l_seg0);
    const uint32_t l_dst1 = swz(l_row1, l_seg1);
    const size_t gA0 = (size_t)(row0 + l_row0) * Hh + l_seg0 * 8;
    const size_t gA1 = (size_t)(row0 + l_row1) * Hh + l_seg1 * 8;

    // ldmatrix per-warp precompute (verified R5 layout)
    int r_mt[2], x_mt[2];
#pragma unroll
    for (int mt = 0; mt < 2; ++mt) {
        r_mt[mt] = wm * 32 + mt * 16 + (lane & 15);
        x_mt[mt] = (r_mt[mt] >> 1) & 3;
    }
    int rb_np[4], xb_np[4];
#pragma unroll
    for (int np = 0; np < 4; ++np) {
        rb_np[np] = wn * 64 + np * 16 + ((lane >> 4) << 3) + (lane & 7);
        xb_np[np] = (rb_np[np] >> 1) & 3;
    }
    const int a_seg0 = lane >> 4;
    const int b_seg0 = (lane >> 3) & 1;

    for (int jj = 0; jj < 4; ++jj) {
        const int jblk = blockIdx.y * 4 + jj;
        const int jbase = jblk * 128;
        const size_t gB0 = (size_t)(jbase + l_row0) * Hh + l_seg0 * 8;
        const size_t gB1 = (size_t)(jbase + l_row1) * Hh + l_seg1 * 8;

        if (tid < 128) {
            ((float*)(smem + SM_DH))[tid] = g_dh[(n << 10) + jbase + tid];
            ((float*)(smem + SM_V))[tid] = v[jbase + tid];
        }
        __syncthreads();  // dh/v visible; smem stages free (prev j fully drained)

        auto cp_stage = [&](int stg, int kb) {
            const uint32_t base = sb + SM_STG + (uint32_t)stg * STAGE_BYTES;
            cp_async16(base + l_dst0, g_Eh + gA0 + kb);
            cp_async16(base + l_dst1, g_Eh + gA1 + kb);
            cp_async16(base + A_BYTES + l_dst0, g_Bh + gB0 + kb);
            cp_async16(base + A_BYTES + l_dst1, g_Bh + gB1 + kb);
        };

        float acc[2][8][4];
#pragma unroll
        for (int mt = 0; mt < 2; ++mt)
#pragma unroll
            for (int nt = 0; nt < 8; ++nt)
#pragma unroll
                for (int e = 0; e < 4; ++e) acc[mt][nt][e] = 0.f;

        // prologue: fill 5 stages
#pragma unroll
        for (int s = 0; s < 5; ++s) {
            cp_stage(s, s * 32);
            CP_COMMIT();
        }

        for (int c = 0; c < 32; ++c) {
            const int pend = (31 - c) < 4 ? (31 - c) : 4;
            switch (pend) {
                case 4: asm volatile("cp.async.wait_group 4;" ::: "memory"); break;
                case 3: asm volatile("cp.async.wait_group 3;" ::: "memory"); break;
                case 2: asm volatile("cp.async.wait_group 2;" ::: "memory"); break;
                case 1: asm volatile("cp.async.wait_group 1;" ::: "memory"); break;
                default: asm volatile("cp.async.wait_group 0;" ::: "memory"); break;
            }
            __syncthreads();
            if (c + 5 < 32) {
                cp_stage((c + 5) % NSTAGE, (c + 5) * 32);
                CP_COMMIT();
            }

            const uint32_t base = sb + SM_STG + (uint32_t)(c % NSTAGE) * STAGE_BYTES;
            const uint32_t sA = base;
            const uint32_t sB = base + A_BYTES;

#pragma unroll
            for (int ks = 0; ks < 2; ++ks) {
                const int aseg = a_seg0 + ks * 2;
                const int bseg = b_seg0 + ks * 2;
                uint32_t ah[2][4];
#pragma unroll
                for (int mt = 0; mt < 2; ++mt) {
                    uint32_t ao = (uint32_t)(r_mt[mt] * 64 + ((aseg ^ x_mt[mt]) << 4));
                    ldsm_x4(ah[mt], sA + ao);
                }
                uint32_t bh[4][4];
#pragma unroll
                for (int np = 0; np < 4; ++np) {
                    uint32_t bo = (uint32_t)(rb_np[np] * 64 + ((bseg ^ xb_np[np]) << 4));
                    ldsm_x4(bh[np], sB + bo);
                }
                // 16 MMAs, all-distinct accumulators (RAW distance 16)
#pragma unroll
                for (int np = 0; np < 4; ++np)
#pragma unroll
                    for (int mt = 0; mt < 2; ++mt) {
                        mma_f16(acc[mt][np * 2 + 0], ah[mt], bh[np][0], bh[np][1]);
                        mma_f16(acc[mt][np * 2 + 1], ah[mt], bh[np][2], bh[np][3]);
                    }
            }
        }

        // epilogue: score partial = sum_j tanh(eh + dh)*v
        const float* dhs = (const float*)(smem + SM_DH);
        const float* vs = (const float*)(smem + SM_V);
        float part[4] = {0.f, 0.f, 0.f, 0.f};
#pragma unroll
        for (int mt = 0; mt < 2; ++mt)
#pragma unroll
            for (int nt = 0; nt < 8; ++nt)
#pragma unroll
                for (int e = 0; e < 4; ++e) {
                    int col = wn * 64 + nt * 8 + (lane & 3) * 2 + (e & 1);
                    part[mt * 2 + (e >> 1)] += tanh_fast(acc[mt][nt][e] + dhs[col]) * vs[col];
                }
#pragma unroll
        for (int p = 0; p < 4; ++p) {
            part[p] += __shfl_xor_sync(0xffffffffu, part[p], 1);
            part[p] += __shfl_xor_sync(0xffffffffu, part[p], 2);
        }
        float* sred = (float*)(smem + SM_SRED);
        if ((lane & 3) == 0) {
#pragma unroll
            for (int mt = 0; mt < 2; ++mt)
#pragma unroll
                for (int rr = 0; rr < 2; ++rr) {
                    int row = wm * 32 + mt * 16 + (lane >> 2) + rr * 8;
                    sred[row * 2 + wn] = part[mt * 2 + rr];
                }
        }
        __syncthreads();
        if (tid < 128) {
            g_scoreP[jblk][row0 + tid] = sred[tid * 2] + sred[tid * 2 + 1];
        }
        __syncthreads();  // sred reads done before next j overwrites
    }
}

// ---------------------------------------------------------------------------
// Masked softmax (sums 8 j-block partials)
// ---------------------------------------------------------------------------
__global__ __launch_bounds__(256) void softmax_kernel(const int* __restrict__ mask,
                                                      float* __restrict__ attn) {
    __shared__ float red[256];
    const int n = blockIdx.x;
    const int tid = threadIdx.x;

    float s[4];
    int msk[4];
    float lmax = -CUDART_INF_F;
#pragma unroll
    for (int q = 0; q < 4; ++q) {
        int l = tid + 256 * q;
        msk[q] = mask[n * Ll + l];
        float acc = 0.f;
#pragma unroll
        for (int p = 0; p < 8; ++p) acc += g_scoreP[p][n * Ll + l];
        s[q] = acc;
        if (!msk[q]) lmax = fmaxf(lmax, s[q]);
    }
    red[tid] = lmax;
    __syncthreads();
    for (int o = 128; o; o >>= 1) {
        if (tid < o) red[tid] = fmaxf(red[tid], red[tid + o]);
        __syncthreads();
    }
    const float mx = red[0];
    __syncthreads();

    float p[4];
    float lsum = 0.f;
#pragma unroll
    for (int q = 0; q < 4; ++q) {
        p[q] = msk[q] ? 0.f : __expf(s[q] - mx);
        lsum += p[q];
    }
    red[tid] = lsum;
    __syncthreads();
    for (int o = 128; o; o >>= 1) {
        if (tid < o) red[tid] += red[tid + o];
        __syncthreads();
    }
    const float inv = 1.0f / red[0];
#pragma unroll
    for (int q = 0; q < 4; ++q) attn[n * Ll + tid + 256 * q] = p[q] * inv;
}

// ---------------------------------------------------------------------------
// Context + reduce
// ---------------------------------------------------------------------------
__global__ __launch_bounds__(128) void context_kernel(const float* __restrict__ E,
                                                      const float* __restrict__ attn) {
    __shared__ float sa[256];
    __shared__ float4 red[128];
    const int n = blockIdx.x, hc = blockIdx.y, lc = blockIdx.z;
    const int tid = threadIdx.x;
    sa[tid] = attn[n * Ll + lc * 256 + tid];
    sa[tid + 128] = attn[n * Ll + lc * 256 + tid + 128];
    __syncthreads();

    const int c = tid & 31;
    const int lg = tid >> 5;
    const float4* Ep = (const float4*)(E + (size_t)n * Ll * Hh) +
                       (size_t)(lc * 256) * 256 + hc * 32 + c;
    float4 acc = make_float4(0.f, 0.f, 0.f, 0.f);
    const int l0 = lg * 64;
#pragma unroll 4
    for (int l = 0; l < 64; ++l) {
        float a = sa[l0 + l];
        float4 e = Ep[(size_t)(l0 + l) * 256];
        acc.x += a * e.x; acc.y += a * e.y;
        acc.z += a * e.z; acc.w += a * e.w;
    }
    red[tid] = acc;
    __syncthreads();
    if (tid < 32) {
        float4 s = red[tid];
#pragma unroll
        for (int g = 1; g < 4; ++g) {
            float4 o = red[tid + 32 * g];
            s.x += o.x; s.y += o.y; s.z += o.z; s.w += o.w;
        }
        g_ctxP[lc][n * 256 + hc * 32 + tid] = s;
    }
}

__global__ __launch_bounds__(256) void ctx_reduce_kernel(float4* __restrict__ ctx4) {
    int i = blockIdx.x * 256 + threadIdx.x;
    float4 a = g_ctxP[0][i], b = g_ctxP[1][i], c = g_ctxP[2][i], d = g_ctxP[3][i];
    ctx4[i] = make_float4(a.x + b.x + c.x + d.x, a.y + b.y + c.y + d.y,
                          a.z + b.z + c.z + d.z, a.w + b.w + c.w + d.w);
}

// ---------------------------------------------------------------------------
extern "C" void kernel_launch(void* const* d_in, const int* in_sizes, int n_in,
                              void* d_out, int out_size) {
    const float* dec  = (const float*)d_in[0];
    const float* E    = (const float*)d_in[1];
    const int*   mask = (const int*)  d_in[2];
    const float* Wh   = (const float*)d_in[3];
    const float* Ws   = (const float*)d_in[4];
    const float* v    = (const float*)d_in[5];

    float* out  = (float*)d_out;
    float* ctx  = out;
    float* attn = out + Nn * Hh;

    cudaFuncSetAttribute(score_kernel, cudaFuncAttributeMaxDynamicSharedMemorySize, SM_TOTAL);

    bconv_kernel<<<(Hh * Hh / 8) / 256, 256>>>(Ws);
    econv_kernel<<<(Nn * Ll * Hh / 8) / 256, 256>>>(E);
    dh_kernel<<<(Nn * Hh * 32) / 256, 256>>>(dec, Wh);
    score_kernel<<<dim3((Nn * Ll) / 128, 2), 256, SM_TOTAL>>>(v);
    softmax_kernel<<<Nn, 256>>>(mask, attn);
    context_kernel<<<dim3(Nn, Hh / 128, 4), 128>>>(E, attn);
    ctx_reduce_kernel<<<(Nn * Hh / 4) / 256, 256>>>((float4*)ctx);
}